// round 7
// baseline (speedup 1.0000x reference)
#include <cuda_runtime.h>
#include <math.h>

#define TT 256
#define BSZ 256

// ---------------- device scratch (no allocation APIs) ----------------
static __device__ float g_xg0f[33554432];   // [T*B][512]
static __device__ float g_xg0r[33554432];   // [T*B][512]
static __device__ float g_xg1 [67108864];   // [T*B][1024] (layer1, reused layer2)
static __device__ float g_bl  [16777216];   // [T*B][256]  bilstm h -> LN1 in place
static __device__ float g_h1  [16777216];   // [T*B][256]  layer1 h -> LN2 in place
static __device__ float g_h2  [16777216];   // [T*B][256]  layer2 h
static __device__ int   g_flags[16384];     // l0:[0,8192) l1:[8192,12288) l2:[12288,16384)

__global__ void zero_flags_kernel() {
    int i = blockIdx.x * blockDim.x + threadIdx.x;
    if (i < 16384) g_flags[i] = 0;
}

// ---------------- GEMM: C[M,N] = A[M,K] @ W[N,K]^T + bias[N] ----------------
// MODE 0: A=inp_embed (t,b)-transposed -> g_xg0f   (K=128,N=512)
// MODE 1: same A                        -> g_xg0r
// MODE 2: A=g_bl                        -> g_xg1    (K=256,N=1024)
// MODE 3: A=g_h1                        -> g_xg1
template<int K, int N, int MODE>
__global__ void __launch_bounds__(256) gemm_kernel(const float* __restrict__ Ap,
                                                   const float* __restrict__ W,
                                                   const float* __restrict__ bias)
{
    __shared__ float As[8 * 128];
    __shared__ float Bs[8 * 128];
    const int cRow = blockIdx.x, cCol = blockIdx.y, tid = threadIdx.x;
    const int tRow = tid >> 4, tCol = tid & 15;
    const int inR = tid >> 1, inC = (tid & 1) << 2;

    const float* Arow;
    {
        int m = cRow * 128 + inR;
        if (MODE <= 1) {
            int t = m >> 8, b = m & 255;
            Arow = Ap + ((size_t)b * TT + t) * 128;
        } else if (MODE == 2) Arow = g_bl + (size_t)m * K;
        else                  Arow = g_h1 + (size_t)m * K;
    }
    float* Cout = (MODE == 0) ? g_xg0f : (MODE == 1) ? g_xg0r : g_xg1;
    const float* Brow = W + (size_t)(cCol * 128 + inR) * K;

    float acc[8][8];
#pragma unroll
    for (int i = 0; i < 8; i++)
#pragma unroll
        for (int j = 0; j < 8; j++) acc[i][j] = 0.f;

    for (int kt = 0; kt < K; kt += 8) {
        float4 av = *(const float4*)(Arow + kt + inC);
        float4 bv = *(const float4*)(Brow + kt + inC);
        As[(inC+0)*128 + inR] = av.x; As[(inC+1)*128 + inR] = av.y;
        As[(inC+2)*128 + inR] = av.z; As[(inC+3)*128 + inR] = av.w;
        Bs[(inC+0)*128 + inR] = bv.x; Bs[(inC+1)*128 + inR] = bv.y;
        Bs[(inC+2)*128 + inR] = bv.z; Bs[(inC+3)*128 + inR] = bv.w;
        __syncthreads();
#pragma unroll
        for (int k = 0; k < 8; k++) {
            float4 a0 = *(const float4*)&As[k*128 + tRow*8];
            float4 a1 = *(const float4*)&As[k*128 + tRow*8 + 4];
            float4 b0 = *(const float4*)&Bs[k*128 + tCol*8];
            float4 b1 = *(const float4*)&Bs[k*128 + tCol*8 + 4];
            float am[8] = {a0.x,a0.y,a0.z,a0.w,a1.x,a1.y,a1.z,a1.w};
            float bn[8] = {b0.x,b0.y,b0.z,b0.w,b1.x,b1.y,b1.z,b1.w};
#pragma unroll
            for (int i = 0; i < 8; i++)
#pragma unroll
                for (int j = 0; j < 8; j++)
                    acc[i][j] = fmaf(am[i], bn[j], acc[i][j]);
        }
        __syncthreads();
    }
    const int n0 = cCol*128 + tCol*8, m0 = cRow*128 + tRow*8;
    float4 bi0 = *(const float4*)(bias + n0);
    float4 bi1 = *(const float4*)(bias + n0 + 4);
#pragma unroll
    for (int i = 0; i < 8; i++) {
        float4 o0 = {acc[i][0]+bi0.x, acc[i][1]+bi0.y, acc[i][2]+bi0.z, acc[i][3]+bi0.w};
        float4 o1 = {acc[i][4]+bi1.x, acc[i][5]+bi1.y, acc[i][6]+bi1.z, acc[i][7]+bi1.w};
        *(float4*)(Cout + (size_t)(m0+i)*N + n0)     = o0;
        *(float4*)(Cout + (size_t)(m0+i)*N + n0 + 4) = o1;
    }
}

__device__ __forceinline__ float sigf(float x) { return 1.f / (1.f + expf(-x)); }

#define DOT4(A_, H_, W_)            \
    A_ = fmaf((H_).x, (W_).x, A_);  \
    A_ = fmaf((H_).y, (W_).y, A_);  \
    A_ = fmaf((H_).z, (W_).z, A_);  \
    A_ = fmaf((H_).w, (W_).w, A_);

// ---------------- layer0 persistent scan, H=128, grid (16,4,2) ----------------
__global__ void __launch_bounds__(256) scan0_kernel(const float* __restrict__ WhhF,
                                                    const float* __restrict__ WhhR)
{
    const int bi = blockIdx.x, jj = blockIdx.y, dir = blockIdx.z;
    const int tid = threadIdx.x, jl = tid & 31, brow = tid >> 5;
    const int j0 = jj * 32, b0 = bi * 16;
    const int WP = 132;

    extern __shared__ float sm[];
    float* Wsm = sm;             // [128][132]
    float* hsm = sm + 128 * WP;  // [16][132]

    const float* Whh = dir ? WhhR : WhhF;
    const float* xg  = dir ? g_xg0r : g_xg0f;
    int* flags = g_flags + dir * 4096 + bi * 256;

    for (int v = tid; v < 128 * 32; v += 256) {
        int r = v >> 5, kc = (v & 31) << 2;
        int grow = ((r >> 5) << 7) + j0 + (r & 31);
        *(float4*)&Wsm[r*WP + kc] = *(const float4*)(Whh + (size_t)grow*128 + kc);
    }
    __syncthreads();

    float c0 = 0.f, c1 = 0.f;
    for (int s = 0; s < 256; s++) {
        const int t = dir ? (255 - s) : s;

        float acc[2][4];
#pragma unroll
        for (int p = 0; p < 2; p++) {
            const float* xr = xg + ((size_t)(t*256 + b0 + brow + p*8)) * 512;
#pragma unroll
            for (int g = 0; g < 4; g++) acc[p][g] = xr[(g << 7) + j0 + jl];
        }

        if (s > 0) {
            const int tp = dir ? (t + 1) : (t - 1);
            if (tid == 0) { while (*(volatile int*)&flags[s-1] < 4) { } }
            __syncthreads();
            for (int v = tid; v < 512; v += 256) {
                int row = v >> 5, kc = (v & 31) << 2;
                *(float4*)&hsm[row*WP + kc] =
                    *(const float4*)(g_bl + ((size_t)(tp*256 + b0 + row))*256 + (dir<<7) + kc);
            }
            __syncthreads();
#pragma unroll 4
            for (int k = 0; k < 128; k += 4) {
                float4 w0 = *(const float4*)&Wsm[(jl     )*WP + k];
                float4 w1 = *(const float4*)&Wsm[(32 + jl)*WP + k];
                float4 w2 = *(const float4*)&Wsm[(64 + jl)*WP + k];
                float4 w3 = *(const float4*)&Wsm[(96 + jl)*WP + k];
                float4 h0 = *(const float4*)&hsm[brow*WP + k];
                float4 h1 = *(const float4*)&hsm[(brow+8)*WP + k];
                DOT4(acc[0][0], h0, w0); DOT4(acc[0][1], h0, w1);
                DOT4(acc[0][2], h0, w2); DOT4(acc[0][3], h0, w3);
                DOT4(acc[1][0], h1, w0); DOT4(acc[1][1], h1, w1);
                DOT4(acc[1][2], h1, w2); DOT4(acc[1][3], h1, w3);
            }
        }

#pragma unroll
        for (int p = 0; p < 2; p++) {
            float iv = sigf(acc[p][0]), fv = sigf(acc[p][1]);
            float gv = tanhf(acc[p][2]), ov = sigf(acc[p][3]);
            float cc = p ? c1 : c0;
            cc = fv * cc + iv * gv;
            if (p) c1 = cc; else c0 = cc;
            g_bl[((size_t)(t*256 + b0 + brow + p*8))*256 + (dir<<7) + j0 + jl] = ov * tanhf(cc);
        }
        __threadfence();
        __syncthreads();
        if (tid == 0) atomicAdd(&flags[s], 1);
    }
}

// ---------------- H2=256 persistent scan (layers 1,2), grid (16,8) ----------------
template<int LAYER>
__global__ void __launch_bounds__(256) scan256_kernel(const float* __restrict__ Whh)
{
    const int bi = blockIdx.x, jj = blockIdx.y;
    const int tid = threadIdx.x, jl = tid & 31, brow = tid >> 5;
    const int j0 = jj * 32, b0 = bi * 16;
    const int WP = 260;

    extern __shared__ float sm[];
    float* Wsm = sm;             // [128][260]
    float* hsm = sm + 128 * WP;  // [16][260]

    float* hbuf = (LAYER == 1) ? g_h1 : g_h2;
    const float* xg = g_xg1;
    int* flags = g_flags + ((LAYER == 1) ? 8192 : 12288) + bi * 256;

    for (int v = tid; v < 128 * 64; v += 256) {
        int r = v >> 6, kc = (v & 63) << 2;
        int grow = ((r >> 5) << 8) + j0 + (r & 31);
        *(float4*)&Wsm[r*WP + kc] = *(const float4*)(Whh + (size_t)grow*256 + kc);
    }
    __syncthreads();

    float c0 = 0.f, c1 = 0.f;
    for (int s = 0; s < 256; s++) {
        const int t = s;

        float acc[2][4];
#pragma unroll
        for (int p = 0; p < 2; p++) {
            const float* xr = xg + ((size_t)(t*256 + b0 + brow + p*8)) * 1024;
#pragma unroll
            for (int g = 0; g < 4; g++) acc[p][g] = xr[(g << 8) + j0 + jl];
        }

        if (s > 0) {
            if (tid == 0) { while (*(volatile int*)&flags[s-1] < 8) { } }
            __syncthreads();
            for (int v = tid; v < 1024; v += 256) {
                int row = v >> 6, kc = (v & 63) << 2;
                *(float4*)&hsm[row*WP + kc] =
                    *(const float4*)(hbuf + ((size_t)((t-1)*256 + b0 + row))*256 + kc);
            }
            __syncthreads();
#pragma unroll 2
            for (int k = 0; k < 256; k += 4) {
                float4 w0 = *(const float4*)&Wsm[(jl     )*WP + k];
                float4 w1 = *(const float4*)&Wsm[(32 + jl)*WP + k];
                float4 w2 = *(const float4*)&Wsm[(64 + jl)*WP + k];
                float4 w3 = *(const float4*)&Wsm[(96 + jl)*WP + k];
                float4 h0 = *(const float4*)&hsm[brow*WP + k];
                float4 h1 = *(const float4*)&hsm[(brow+8)*WP + k];
                DOT4(acc[0][0], h0, w0); DOT4(acc[0][1], h0, w1);
                DOT4(acc[0][2], h0, w2); DOT4(acc[0][3], h0, w3);
                DOT4(acc[1][0], h1, w0); DOT4(acc[1][1], h1, w1);
                DOT4(acc[1][2], h1, w2); DOT4(acc[1][3], h1, w3);
            }
        }

#pragma unroll
        for (int p = 0; p < 2; p++) {
            float iv = sigf(acc[p][0]), fv = sigf(acc[p][1]);
            float gv = tanhf(acc[p][2]), ov = sigf(acc[p][3]);
            float cc = p ? c1 : c0;
            cc = fv * cc + iv * gv;
            if (p) c1 = cc; else c0 = cc;
            hbuf[((size_t)(t*256 + b0 + brow + p*8))*256 + j0 + jl] = ov * tanhf(cc);
        }
        __threadfence();
        __syncthreads();
        if (tid == 0) atomicAdd(&flags[s], 1);
    }
}

// ---------------- LayerNorm over last dim (256), warp per row ----------------
// WHICH 1: out = LN(g_bl) in place.  WHICH 2: out = LN(g_h1 + g_bl) into g_h1.
template<int WHICH>
__global__ void __launch_bounds__(256) ln_kernel(const float* __restrict__ gam,
                                                 const float* __restrict__ bet)
{
    const int warp = threadIdx.x >> 5, lane = threadIdx.x & 31;
    const size_t row = (size_t)blockIdx.x * 8 + warp;
    const float* x = (WHICH == 1) ? g_bl : g_h1;
    float* out = (WHICH == 1) ? g_bl : g_h1;
    const size_t base = row * 256 + lane * 8;

    float4 a0 = *(const float4*)(x + base);
    float4 a1 = *(const float4*)(x + base + 4);
    if (WHICH == 2) {
        float4 r0 = *(const float4*)(g_bl + base);
        float4 r1 = *(const float4*)(g_bl + base + 4);
        a0.x += r0.x; a0.y += r0.y; a0.z += r0.z; a0.w += r0.w;
        a1.x += r1.x; a1.y += r1.y; a1.z += r1.z; a1.w += r1.w;
    }
    float v[8] = {a0.x,a0.y,a0.z,a0.w,a1.x,a1.y,a1.z,a1.w};
    float s = 0.f;
#pragma unroll
    for (int i = 0; i < 8; i++) s += v[i];
#pragma unroll
    for (int o = 16; o; o >>= 1) s += __shfl_xor_sync(0xffffffffu, s, o);
    float mu = s * (1.f / 256.f);
    float ss = 0.f;
#pragma unroll
    for (int i = 0; i < 8; i++) { v[i] -= mu; ss += v[i] * v[i]; }
#pragma unroll
    for (int o = 16; o; o >>= 1) ss += __shfl_xor_sync(0xffffffffu, ss, o);
    float rs = rsqrtf(ss * (1.f / 256.f) + 1e-5f);
    const int c0 = lane * 8;
    float4 g0 = *(const float4*)(gam + c0), g1 = *(const float4*)(gam + c0 + 4);
    float4 b0 = *(const float4*)(bet + c0), b1 = *(const float4*)(bet + c0 + 4);
    float gg[8] = {g0.x,g0.y,g0.z,g0.w,g1.x,g1.y,g1.z,g1.w};
    float bb[8] = {b0.x,b0.y,b0.z,b0.w,b1.x,b1.y,b1.z,b1.w};
    float4 o0, o1;
    o0.x = v[0]*rs*gg[0]+bb[0]; o0.y = v[1]*rs*gg[1]+bb[1];
    o0.z = v[2]*rs*gg[2]+bb[2]; o0.w = v[3]*rs*gg[3]+bb[3];
    o1.x = v[4]*rs*gg[4]+bb[4]; o1.y = v[5]*rs*gg[5]+bb[5];
    o1.z = v[6]*rs*gg[6]+bb[6]; o1.w = v[7]*rs*gg[7]+bb[7];
    *(float4*)(out + base) = o0;
    *(float4*)(out + base + 4) = o1;
}

// ---------------- gather + affine + relu (auto int32/int64 idx) ----------------
__global__ void __launch_bounds__(256) gather_kernel(const int* __restrict__ idx32,
                                                     const float* __restrict__ bn_g,
                                                     const float* __restrict__ bn_b,
                                                     float* __restrict__ out)
{
    __shared__ int sidx;
    const int b = blockIdx.x, j = threadIdx.x;
    if (j < 32) {
        int v = idx32[2 * j + 1];
        unsigned m = __ballot_sync(0xffffffffu, v != 0);
        if (j == 0) sidx = (m == 0) ? idx32[2 * b] : idx32[b];
    }
    __syncthreads();
    const int t = sidx;
    float scale = rsqrtf(1.0f + 1e-5f);
    float y = g_h2[((size_t)(t*256 + b))*256 + j] * scale * bn_g[j] + bn_b[j];
    out[(size_t)b * 256 + j] = fmaxf(y, 0.f);
}

// ---------------- launch ----------------
extern "C" void kernel_launch(void* const* d_in, const int* in_sizes, int n_in,
                              void* d_out, int out_size)
{
    const float* inp   = (const float*)d_in[0];
    const int*   idx   = (const int*)  d_in[1];
    const float* Wih_f = (const float*)d_in[2];
    const float* Whh_f = (const float*)d_in[3];
    const float* b_f   = (const float*)d_in[4];
    const float* Wih_r = (const float*)d_in[5];
    const float* Whh_r = (const float*)d_in[6];
    const float* b_r   = (const float*)d_in[7];
    const float* ln1_g = (const float*)d_in[8];
    const float* ln1_b = (const float*)d_in[9];
    const float* W1ih  = (const float*)d_in[10];
    const float* W1hh  = (const float*)d_in[11];
    const float* b1    = (const float*)d_in[12];
    const float* ln2_g = (const float*)d_in[13];
    const float* ln2_b = (const float*)d_in[14];
    const float* W2ih  = (const float*)d_in[15];
    const float* W2hh  = (const float*)d_in[16];
    const float* b2    = (const float*)d_in[17];
    const float* bn_g  = (const float*)d_in[18];
    const float* bn_b  = (const float*)d_in[19];
    float* out = (float*)d_out;

    cudaFuncSetAttribute(scan0_kernel,    cudaFuncAttributeMaxDynamicSharedMemorySize, 76032);
    cudaFuncSetAttribute(scan256_kernel<1>, cudaFuncAttributeMaxDynamicSharedMemorySize, 149760);
    cudaFuncSetAttribute(scan256_kernel<2>, cudaFuncAttributeMaxDynamicSharedMemorySize, 149760);

    zero_flags_kernel<<<64, 256>>>();
    gemm_kernel<128, 512, 0><<<dim3(512, 4), 256>>>(inp, Wih_f, b_f);
    gemm_kernel<128, 512, 1><<<dim3(512, 4), 256>>>(inp, Wih_r, b_r);
    scan0_kernel<<<dim3(16, 4, 2), 256, 76032>>>(Whh_f, Whh_r);
    ln_kernel<1><<<8192, 256>>>(ln1_g, ln1_b);
    gemm_kernel<256, 1024, 2><<<dim3(512, 8), 256>>>(nullptr, W1ih, b1);
    scan256_kernel<1><<<dim3(16, 8), 256, 149760>>>(W1hh);
    ln_kernel<2><<<8192, 256>>>(ln2_g, ln2_b);
    gemm_kernel<256, 1024, 3><<<dim3(512, 8), 256>>>(nullptr, W2ih, b2);
    scan256_kernel<2><<<dim3(16, 8), 256, 149760>>>(W2hh);
    gather_kernel<<<256, 256>>>(idx, bn_g, bn_b, out);
}

// round 8
// speedup vs baseline: 1.2966x; 1.2966x over previous
#include <cuda_runtime.h>
#include <math.h>

#define TT 256
#define BSZ 256

// ---------------- device scratch (no allocation APIs) ----------------
static __device__ float g_xg0f[33554432];   // [T*B][512]
static __device__ float g_xg0r[33554432];   // [T*B][512]
static __device__ float g_xg1 [67108864];   // [T*B][1024] (layer1, reused layer2)
static __device__ float g_bl  [16777216];   // [T*B][256]  bilstm h -> LN1 in place
static __device__ float g_h1  [16777216];   // [T*B][256]  layer1 h -> LN2 in place
static __device__ float g_h2  [16777216];   // [T*B][256]  layer2 h
static __device__ int   g_flags[16384];

__global__ void zero_flags_kernel() {
    int i = blockIdx.x * blockDim.x + threadIdx.x;
    if (i < 16384) g_flags[i] = 0;
}

// ---------------- tf32 helpers ----------------
__device__ __forceinline__ unsigned f2tf32(float x) {
    unsigned r;
    asm("cvt.rna.tf32.f32 %0, %1;" : "=r"(r) : "f"(x));
    return r;
}
__device__ __forceinline__ void mma_tf32(float c[4], const unsigned a[4], const unsigned b[2]) {
    asm volatile(
        "mma.sync.aligned.m16n8k8.row.col.f32.tf32.tf32.f32 "
        "{%0,%1,%2,%3}, {%4,%5,%6,%7}, {%8,%9}, {%0,%1,%2,%3};"
        : "+f"(c[0]), "+f"(c[1]), "+f"(c[2]), "+f"(c[3])
        : "r"(a[0]), "r"(a[1]), "r"(a[2]), "r"(a[3]), "r"(b[0]), "r"(b[1]));
}

// ---------------- tf32 tensor-core GEMM: C[M,N] = A[M,K] @ W[N,K]^T + bias ----
// MODE 0: A=inp_embed (t,b)-transposed -> g_xg0f   (K=128,N=512)
// MODE 1: same A                        -> g_xg0r
// MODE 2: A=g_bl                        -> g_xg1    (K=256,N=1024)
// MODE 3: A=g_h1                        -> g_xg1
// CTA tile 128x128, BK=32, 8 warps (4M x 2N), warp tile 32x64, m16n8k8.
template<int K, int N, int MODE>
__global__ void __launch_bounds__(256) mma_gemm(const float* __restrict__ Ap,
                                                const float* __restrict__ W,
                                                const float* __restrict__ bias)
{
    __shared__ unsigned As[128 * 36];   // stride 36 -> conflict-free fragment loads
    __shared__ unsigned Bs[128 * 36];
    const int tid = threadIdx.x, lane = tid & 31, wid = tid >> 5;
    const int warpM = wid >> 1, warpN = wid & 1;
    const int cRow = blockIdx.x, cCol = blockIdx.y;

    float acc[2][8][4];
#pragma unroll
    for (int mt = 0; mt < 2; mt++)
#pragma unroll
        for (int nt = 0; nt < 8; nt++)
#pragma unroll
            for (int i = 0; i < 4; i++) acc[mt][nt][i] = 0.f;

    for (int kt = 0; kt < K; kt += 32) {
#pragma unroll
        for (int i = 0; i < 4; i++) {
            int f = tid + i * 256;          // float4 index in 128x32 tile
            int row = f >> 3, kc = (f & 7) << 2;
            const float* ap;
            if (MODE <= 1) {
                int m = cRow * 128 + row;
                ap = Ap + ((size_t)(m & 255) * TT + (m >> 8)) * 128 + kt + kc;
            } else if (MODE == 2) {
                ap = g_bl + (size_t)(cRow * 128 + row) * K + kt + kc;
            } else {
                ap = g_h1 + (size_t)(cRow * 128 + row) * K + kt + kc;
            }
            float4 av = *(const float4*)ap;
            float4 bv = *(const float4*)(W + (size_t)(cCol * 128 + row) * K + kt + kc);
            unsigned* ad = &As[row * 36 + kc];
            ad[0] = f2tf32(av.x); ad[1] = f2tf32(av.y);
            ad[2] = f2tf32(av.z); ad[3] = f2tf32(av.w);
            unsigned* bd = &Bs[row * 36 + kc];
            bd[0] = f2tf32(bv.x); bd[1] = f2tf32(bv.y);
            bd[2] = f2tf32(bv.z); bd[3] = f2tf32(bv.w);
        }
        __syncthreads();

#pragma unroll
        for (int kk = 0; kk < 32; kk += 8) {
            const int k0 = kk + (lane & 3);
            unsigned a[2][4], b[8][2];
#pragma unroll
            for (int mt = 0; mt < 2; mt++) {
                int row = warpM * 32 + mt * 16 + (lane >> 2);
                a[mt][0] = As[row * 36 + k0];
                a[mt][1] = As[(row + 8) * 36 + k0];
                a[mt][2] = As[row * 36 + k0 + 4];
                a[mt][3] = As[(row + 8) * 36 + k0 + 4];
            }
#pragma unroll
            for (int nt = 0; nt < 8; nt++) {
                int col = warpN * 64 + nt * 8 + (lane >> 2);
                b[nt][0] = Bs[col * 36 + k0];
                b[nt][1] = Bs[col * 36 + k0 + 4];
            }
#pragma unroll
            for (int mt = 0; mt < 2; mt++)
#pragma unroll
                for (int nt = 0; nt < 8; nt++)
                    mma_tf32(acc[mt][nt], a[mt], b[nt]);
        }
        __syncthreads();
    }

    float* Cout = (MODE == 0) ? g_xg0f : (MODE == 1) ? g_xg0r : g_xg1;
#pragma unroll
    for (int nt = 0; nt < 8; nt++) {
        int c = cCol * 128 + warpN * 64 + nt * 8 + (lane & 3) * 2;
        float bx = bias[c], by = bias[c + 1];
#pragma unroll
        for (int mt = 0; mt < 2; mt++) {
            int r0 = cRow * 128 + warpM * 32 + mt * 16 + (lane >> 2);
            float2 o0 = {acc[mt][nt][0] + bx, acc[mt][nt][1] + by};
            float2 o1 = {acc[mt][nt][2] + bx, acc[mt][nt][3] + by};
            *(float2*)(Cout + (size_t)r0 * N + c)       = o0;
            *(float2*)(Cout + (size_t)(r0 + 8) * N + c) = o1;
        }
    }
}

__device__ __forceinline__ float sigf(float x) { return 1.f / (1.f + expf(-x)); }

#define DOT4(A_, H_, W_)            \
    A_ = fmaf((H_).x, (W_).x, A_);  \
    A_ = fmaf((H_).y, (W_).y, A_);  \
    A_ = fmaf((H_).z, (W_).z, A_);  \
    A_ = fmaf((H_).w, (W_).w, A_);

// ---------------- layer0 persistent scan, H=128, grid (16,4,2) ----------------
// Wsm: unpadded stride 128 with XOR swizzle kc4^=(row&7) -> conflict-free LDS.128
__global__ void __launch_bounds__(256) scan0_kernel(const float* __restrict__ WhhF,
                                                    const float* __restrict__ WhhR)
{
    const int bi = blockIdx.x, jj = blockIdx.y, dir = blockIdx.z;
    const int tid = threadIdx.x, jl = tid & 31, brow = tid >> 5;
    const int j0 = jj * 32, b0 = bi * 16;
    const int HP = 132;

    extern __shared__ float sm[];
    float* Wsm = sm;               // [128][128] swizzled
    float* hsm = sm + 128 * 128;   // [16][132]

    const float* Whh = dir ? WhhR : WhhF;
    const float* xg  = dir ? g_xg0r : g_xg0f;
    int* flags = g_flags + dir * 4096 + bi * 256;

    for (int v = tid; v < 128 * 32; v += 256) {
        int r = v >> 5, kc4 = v & 31;
        int grow = ((r >> 5) << 7) + j0 + (r & 31);
        *(float4*)&Wsm[r * 128 + ((kc4 ^ (r & 7)) << 2)] =
            *(const float4*)(Whh + (size_t)grow * 128 + (kc4 << 2));
    }
    __syncthreads();

    float c0 = 0.f, c1 = 0.f;
    for (int s = 0; s < 256; s++) {
        const int t = dir ? (255 - s) : s;

        float acc[2][4];
#pragma unroll
        for (int p = 0; p < 2; p++) {
            const float* xr = xg + ((size_t)(t * 256 + b0 + brow + p * 8)) * 512;
#pragma unroll
            for (int g = 0; g < 4; g++) acc[p][g] = xr[(g << 7) + j0 + jl];
        }

        if (s > 0) {
            const int tp = dir ? (t + 1) : (t - 1);
            if (tid == 0) { while (*(volatile int*)&flags[s - 1] < 4) { } }
            __syncthreads();
            for (int v = tid; v < 512; v += 256) {
                int row = v >> 5, kc = (v & 31) << 2;
                *(float4*)&hsm[row * HP + kc] =
                    *(const float4*)(g_bl + ((size_t)(tp * 256 + b0 + row)) * 256 + (dir << 7) + kc);
            }
            __syncthreads();
#pragma unroll 4
            for (int k = 0; k < 128; k += 4) {
                const int sw = ((k >> 2) ^ (jl & 7)) << 2;
                float4 w0 = *(const float4*)&Wsm[(jl      ) * 128 + sw];
                float4 w1 = *(const float4*)&Wsm[(32 + jl) * 128 + sw];
                float4 w2 = *(const float4*)&Wsm[(64 + jl) * 128 + sw];
                float4 w3 = *(const float4*)&Wsm[(96 + jl) * 128 + sw];
                float4 h0 = *(const float4*)&hsm[brow * HP + k];
                float4 h1 = *(const float4*)&hsm[(brow + 8) * HP + k];
                DOT4(acc[0][0], h0, w0); DOT4(acc[0][1], h0, w1);
                DOT4(acc[0][2], h0, w2); DOT4(acc[0][3], h0, w3);
                DOT4(acc[1][0], h1, w0); DOT4(acc[1][1], h1, w1);
                DOT4(acc[1][2], h1, w2); DOT4(acc[1][3], h1, w3);
            }
        }

#pragma unroll
        for (int p = 0; p < 2; p++) {
            float iv = sigf(acc[p][0]), fv = sigf(acc[p][1]);
            float gv = tanhf(acc[p][2]), ov = sigf(acc[p][3]);
            float cc = p ? c1 : c0;
            cc = fv * cc + iv * gv;
            if (p) c1 = cc; else c0 = cc;
            g_bl[((size_t)(t * 256 + b0 + brow + p * 8)) * 256 + (dir << 7) + j0 + jl] = ov * tanhf(cc);
        }
        __threadfence();
        __syncthreads();
        if (tid == 0) atomicAdd(&flags[s], 1);
    }
}

// ---------------- H2=256 persistent scan (layers 1,2), grid (16,8) ----------------
template<int LAYER>
__global__ void __launch_bounds__(256) scan256_kernel(const float* __restrict__ Whh)
{
    const int bi = blockIdx.x, jj = blockIdx.y;
    const int tid = threadIdx.x, jl = tid & 31, brow = tid >> 5;
    const int j0 = jj * 32, b0 = bi * 16;
    const int HP = 260;

    extern __shared__ float sm[];
    float* Wsm = sm;               // [128][256] swizzled
    float* hsm = sm + 128 * 256;   // [16][260]

    float* hbuf = (LAYER == 1) ? g_h1 : g_h2;
    const float* xg = g_xg1;
    int* flags = g_flags + ((LAYER == 1) ? 8192 : 12288) + bi * 256;

    for (int v = tid; v < 128 * 64; v += 256) {
        int r = v >> 6, kc4 = v & 63;
        int grow = ((r >> 5) << 8) + j0 + (r & 31);
        *(float4*)&Wsm[r * 256 + ((kc4 ^ (r & 7)) << 2)] =
            *(const float4*)(Whh + (size_t)grow * 256 + (kc4 << 2));
    }
    __syncthreads();

    float c0 = 0.f, c1 = 0.f;
    for (int s = 0; s < 256; s++) {
        const int t = s;

        float acc[2][4];
#pragma unroll
        for (int p = 0; p < 2; p++) {
            const float* xr = xg + ((size_t)(t * 256 + b0 + brow + p * 8)) * 1024;
#pragma unroll
            for (int g = 0; g < 4; g++) acc[p][g] = xr[(g << 8) + j0 + jl];
        }

        if (s > 0) {
            if (tid == 0) { while (*(volatile int*)&flags[s - 1] < 8) { } }
            __syncthreads();
            for (int v = tid; v < 1024; v += 256) {
                int row = v >> 6, kc = (v & 63) << 2;
                *(float4*)&hsm[row * HP + kc] =
                    *(const float4*)(hbuf + ((size_t)((t - 1) * 256 + b0 + row)) * 256 + kc);
            }
            __syncthreads();
#pragma unroll 2
            for (int k = 0; k < 256; k += 4) {
                const int sw = ((k >> 2) ^ (jl & 7)) << 2;
                float4 w0 = *(const float4*)&Wsm[(jl      ) * 256 + sw];
                float4 w1 = *(const float4*)&Wsm[(32 + jl) * 256 + sw];
                float4 w2 = *(const float4*)&Wsm[(64 + jl) * 256 + sw];
                float4 w3 = *(const float4*)&Wsm[(96 + jl) * 256 + sw];
                float4 h0 = *(const float4*)&hsm[brow * HP + k];
                float4 h1 = *(const float4*)&hsm[(brow + 8) * HP + k];
                DOT4(acc[0][0], h0, w0); DOT4(acc[0][1], h0, w1);
                DOT4(acc[0][2], h0, w2); DOT4(acc[0][3], h0, w3);
                DOT4(acc[1][0], h1, w0); DOT4(acc[1][1], h1, w1);
                DOT4(acc[1][2], h1, w2); DOT4(acc[1][3], h1, w3);
            }
        }

#pragma unroll
        for (int p = 0; p < 2; p++) {
            float iv = sigf(acc[p][0]), fv = sigf(acc[p][1]);
            float gv = tanhf(acc[p][2]), ov = sigf(acc[p][3]);
            float cc = p ? c1 : c0;
            cc = fv * cc + iv * gv;
            if (p) c1 = cc; else c0 = cc;
            hbuf[((size_t)(t * 256 + b0 + brow + p * 8)) * 256 + j0 + jl] = ov * tanhf(cc);
        }
        __threadfence();
        __syncthreads();
        if (tid == 0) atomicAdd(&flags[s], 1);
    }
}

// ---------------- LayerNorm over last dim (256), warp per row ----------------
template<int WHICH>
__global__ void __launch_bounds__(256) ln_kernel(const float* __restrict__ gam,
                                                 const float* __restrict__ bet)
{
    const int warp = threadIdx.x >> 5, lane = threadIdx.x & 31;
    const size_t row = (size_t)blockIdx.x * 8 + warp;
    const float* x = (WHICH == 1) ? g_bl : g_h1;
    float* out = (WHICH == 1) ? g_bl : g_h1;
    const size_t base = row * 256 + lane * 8;

    float4 a0 = *(const float4*)(x + base);
    float4 a1 = *(const float4*)(x + base + 4);
    if (WHICH == 2) {
        float4 r0 = *(const float4*)(g_bl + base);
        float4 r1 = *(const float4*)(g_bl + base + 4);
        a0.x += r0.x; a0.y += r0.y; a0.z += r0.z; a0.w += r0.w;
        a1.x += r1.x; a1.y += r1.y; a1.z += r1.z; a1.w += r1.w;
    }
    float v[8] = {a0.x,a0.y,a0.z,a0.w,a1.x,a1.y,a1.z,a1.w};
    float s = 0.f;
#pragma unroll
    for (int i = 0; i < 8; i++) s += v[i];
#pragma unroll
    for (int o = 16; o; o >>= 1) s += __shfl_xor_sync(0xffffffffu, s, o);
    float mu = s * (1.f / 256.f);
    float ss = 0.f;
#pragma unroll
    for (int i = 0; i < 8; i++) { v[i] -= mu; ss += v[i] * v[i]; }
#pragma unroll
    for (int o = 16; o; o >>= 1) ss += __shfl_xor_sync(0xffffffffu, ss, o);
    float rs = rsqrtf(ss * (1.f / 256.f) + 1e-5f);
    const int c0 = lane * 8;
    float4 g0 = *(const float4*)(gam + c0), g1 = *(const float4*)(gam + c0 + 4);
    float4 b0 = *(const float4*)(bet + c0), b1 = *(const float4*)(bet + c0 + 4);
    float gg[8] = {g0.x,g0.y,g0.z,g0.w,g1.x,g1.y,g1.z,g1.w};
    float bb[8] = {b0.x,b0.y,b0.z,b0.w,b1.x,b1.y,b1.z,b1.w};
    float4 o0, o1;
    o0.x = v[0]*rs*gg[0]+bb[0]; o0.y = v[1]*rs*gg[1]+bb[1];
    o0.z = v[2]*rs*gg[2]+bb[2]; o0.w = v[3]*rs*gg[3]+bb[3];
    o1.x = v[4]*rs*gg[4]+bb[4]; o1.y = v[5]*rs*gg[5]+bb[5];
    o1.z = v[6]*rs*gg[6]+bb[6]; o1.w = v[7]*rs*gg[7]+bb[7];
    *(float4*)(out + base) = o0;
    *(float4*)(out + base + 4) = o1;
}

// ---------------- gather + affine + relu (auto int32/int64 idx) ----------------
__global__ void __launch_bounds__(256) gather_kernel(const int* __restrict__ idx32,
                                                     const float* __restrict__ bn_g,
                                                     const float* __restrict__ bn_b,
                                                     float* __restrict__ out)
{
    __shared__ int sidx;
    const int b = blockIdx.x, j = threadIdx.x;
    if (j < 32) {
        int v = idx32[2 * j + 1];
        unsigned m = __ballot_sync(0xffffffffu, v != 0);
        if (j == 0) sidx = (m == 0) ? idx32[2 * b] : idx32[b];
    }
    __syncthreads();
    const int t = sidx;
    float scale = rsqrtf(1.0f + 1e-5f);
    float y = g_h2[((size_t)(t * 256 + b)) * 256 + j] * scale * bn_g[j] + bn_b[j];
    out[(size_t)b * 256 + j] = fmaxf(y, 0.f);
}

// ---------------- launch ----------------
extern "C" void kernel_launch(void* const* d_in, const int* in_sizes, int n_in,
                              void* d_out, int out_size)
{
    const float* inp   = (const float*)d_in[0];
    const int*   idx   = (const int*)  d_in[1];
    const float* Wih_f = (const float*)d_in[2];
    const float* Whh_f = (const float*)d_in[3];
    const float* b_f   = (const float*)d_in[4];
    const float* Wih_r = (const float*)d_in[5];
    const float* Whh_r = (const float*)d_in[6];
    const float* b_r   = (const float*)d_in[7];
    const float* ln1_g = (const float*)d_in[8];
    const float* ln1_b = (const float*)d_in[9];
    const float* W1ih  = (const float*)d_in[10];
    const float* W1hh  = (const float*)d_in[11];
    const float* b1    = (const float*)d_in[12];
    const float* ln2_g = (const float*)d_in[13];
    const float* ln2_b = (const float*)d_in[14];
    const float* W2ih  = (const float*)d_in[15];
    const float* W2hh  = (const float*)d_in[16];
    const float* b2    = (const float*)d_in[17];
    const float* bn_g  = (const float*)d_in[18];
    const float* bn_b  = (const float*)d_in[19];
    float* out = (float*)d_out;

    cudaFuncSetAttribute(scan0_kernel,      cudaFuncAttributeMaxDynamicSharedMemorySize, 73984);
    cudaFuncSetAttribute(scan256_kernel<1>, cudaFuncAttributeMaxDynamicSharedMemorySize, 147712);
    cudaFuncSetAttribute(scan256_kernel<2>, cudaFuncAttributeMaxDynamicSharedMemorySize, 147712);

    zero_flags_kernel<<<64, 256>>>();
    mma_gemm<128, 512, 0><<<dim3(512, 4), 256>>>(inp, Wih_f, b_f);
    mma_gemm<128, 512, 1><<<dim3(512, 4), 256>>>(inp, Wih_r, b_r);
    scan0_kernel<<<dim3(16, 4, 2), 256, 73984>>>(Whh_f, Whh_r);
    ln_kernel<1><<<8192, 256>>>(ln1_g, ln1_b);
    mma_gemm<256, 1024, 2><<<dim3(512, 8), 256>>>(nullptr, W1ih, b1);
    scan256_kernel<1><<<dim3(16, 8), 256, 147712>>>(W1hh);
    ln_kernel<2><<<8192, 256>>>(ln2_g, ln2_b);
    mma_gemm<256, 1024, 3><<<dim3(512, 8), 256>>>(nullptr, W2ih, b2);
    scan256_kernel<2><<<dim3(16, 8), 256, 147712>>>(W2hh);
    gather_kernel<<<256, 256>>>(idx, bn_g, bn_b, out);
}